// round 11
// baseline (speedup 1.0000x reference)
#include <cuda_runtime.h>
#include <cuda_bf16.h>
#include <math.h>
#include <stdint.h>

// ---------------- Problem constants ----------------
#define N_TOK 16384
#define D_IN  1024
#define D_OUT 1024
#define N_EXP 8
#define RANK  16
#define SCALING 2.0f   // ALPHA / R

// ---------------- Device scratch ----------------
__device__ __nv_bfloat16 g_Ah[(size_t)N_TOK * D_IN];   // tokens hi   [n][k]
__device__ __nv_bfloat16 g_Al[(size_t)N_TOK * D_IN];   // tokens lo
__device__ __nv_bfloat16 g_Wh[(size_t)D_IN * D_OUT];   // W_base hi   [k][n]
__device__ __nv_bfloat16 g_Wl[(size_t)D_IN * D_OUT];
__device__ __nv_bfloat16 g_Bc_h[D_IN * 160];           // [A_flat|Wg|0] hi [k][j]
__device__ __nv_bfloat16 g_Bc_l[D_IN * 160];
__device__ __nv_bfloat16 g_Bf_h[128 * D_OUT];          // B_flat hi   [j][m]
__device__ __nv_bfloat16 g_Bf_l[128 * D_OUT];
__device__ __nv_bfloat16 g_Hh[(size_t)N_TOK * 128];    // gated H hi  [n][j]
__device__ __nv_bfloat16 g_Hl[(size_t)N_TOK * 128];

// ---------------- PTX helpers ----------------
__device__ __forceinline__ uint32_t s2u(const void* p) {
    uint32_t a;
    asm("{ .reg .u64 t; cvta.to.shared.u64 t, %1; cvt.u32.u64 %0, t; }"
        : "=r"(a) : "l"(p));
    return a;
}
__device__ __forceinline__ void cp16(uint32_t dst, const void* src) {
    asm volatile("cp.async.cg.shared.global [%0], [%1], 16;"
                 :: "r"(dst), "l"(__cvta_generic_to_global(src)));
}
#define CP_COMMIT() asm volatile("cp.async.commit_group;" ::: "memory")

__device__ __forceinline__ void ldsm4(uint32_t* r, uint32_t a) {
    asm volatile("ldmatrix.sync.aligned.m8n8.x4.shared.b16 {%0,%1,%2,%3}, [%4];"
                 : "=r"(r[0]), "=r"(r[1]), "=r"(r[2]), "=r"(r[3]) : "r"(a));
}
__device__ __forceinline__ void ldsm4t(uint32_t* r, uint32_t a) {
    asm volatile("ldmatrix.sync.aligned.m8n8.x4.trans.shared.b16 {%0,%1,%2,%3}, [%4];"
                 : "=r"(r[0]), "=r"(r[1]), "=r"(r[2]), "=r"(r[3]) : "r"(a));
}
__device__ __forceinline__ void mma_bf16(float* c, const uint32_t* a,
                                         uint32_t b0, uint32_t b1) {
    asm volatile(
        "mma.sync.aligned.m16n8k16.row.col.f32.bf16.bf16.f32 "
        "{%0,%1,%2,%3}, {%4,%5,%6,%7}, {%8,%9}, {%0,%1,%2,%3};"
        : "+f"(c[0]), "+f"(c[1]), "+f"(c[2]), "+f"(c[3])
        : "r"(a[0]), "r"(a[1]), "r"(a[2]), "r"(a[3]), "r"(b0), "r"(b1));
}

// ---------------- Conversion helpers ----------------
__device__ __forceinline__ void split2(float v, __nv_bfloat16& h, __nv_bfloat16& l) {
    h = __float2bfloat16(v);
    l = __float2bfloat16(v - __bfloat162float(h));
}
__device__ __forceinline__ uint32_t pack2(__nv_bfloat16 a, __nv_bfloat16 b) {
    return (uint32_t)__bfloat16_as_ushort(a) | ((uint32_t)__bfloat16_as_ushort(b) << 16);
}
__device__ __forceinline__ void split_store4(const float4& v, uint2* ph, uint2* pl) {
    __nv_bfloat16 h0, h1, h2, h3, l0, l1, l2, l3;
    split2(v.x, h0, l0); split2(v.y, h1, l1);
    split2(v.z, h2, l2); split2(v.w, h3, l3);
    *ph = make_uint2(pack2(h0, h1), pack2(h2, h3));
    *pl = make_uint2(pack2(l0, l1), pack2(l2, l3));
}

// ---------------- Fused conversion kernel ----------------
__global__ __launch_bounds__(256) void conv_all(
    const float4* __restrict__ tok, const float4* __restrict__ W,
    const float*  __restrict__ A,   const float* __restrict__ Wg,
    const float4* __restrict__ B) {
    const int b = blockIdx.x;
    if (b < 16384) {
        size_t i = (size_t)b * 256 + threadIdx.x;
        split_store4(tok[i], (uint2*)g_Ah + i, (uint2*)g_Al + i);
    } else if (b < 17408) {
        size_t i = (size_t)(b - 16384) * 256 + threadIdx.x;
        split_store4(W[i], (uint2*)g_Wh + i, (uint2*)g_Wl + i);
    } else if (b < 18048) {
        int i = (b - 17408) * 256 + threadIdx.x;
        if (i < 160 * 1024) {
            int d = i / 160, j = i % 160;
            float v = 0.f;
            if (j < 128) { int e = j >> 4, r = j & 15; v = A[(size_t)e * 16384 + d * 16 + r]; }
            else if (j < 136) v = Wg[(size_t)d * 8 + (j - 128)];
            __nv_bfloat16 h, l; split2(v, h, l);
            g_Bc_h[i] = h; g_Bc_l[i] = l;
        }
    } else {
        size_t i = (size_t)(b - 18048) * 256 + threadIdx.x;
        split_store4(B[i], (uint2*)g_Bf_h + i, (uint2*)g_Bf_l + i);
    }
}

// ---------------- GEMM1 + fused router ----------------
// h_ext[128,160] = tokens @ Bc ; then per-row top-2 softmax, gated H, outputs.
// BM=128, BN=160, BK=32, 256 threads, 8 warps 4(m)x2(n), warp tile 32x80.
__global__ __launch_bounds__(256, 2) void gemm1_mma(float* __restrict__ out_logits,
                                                    float* __restrict__ out_sel,
                                                    float* __restrict__ out_wts) {
    constexpr int BM = 128, BN = 160, BK = 32, NST = 4;
    constexpr int HN = BN / 2, N8 = HN / 8, NT2 = N8 / 2;   // 80, 10, 5
    constexpr int LDA = BK + 8, LDB = BN + 8;
    constexpr uint32_t ASZ = BM * LDA * 2, BSZ = BK * LDB * 2;
    constexpr uint32_t STG = ASZ + BSZ;
    constexpr int LDH = 164;    // fp32 row stride for epilogue staging

    extern __shared__ __align__(16) char smem[];
    const uint32_t sA = s2u(smem);
    const uint32_t sB = sA + ASZ;
    float* hsm = (float*)smem;  // reused at epilogue: [128][164] fp32 = 83,968 B

    const int tid = threadIdx.x, w = tid >> 5, lane = tid & 31;
    const int wm = w & 3, wn = w >> 2;
    const int lr = lane & 15, lc8 = (lane >> 4) * 8;
    const int bm = blockIdx.y * BM;

    const __nv_bfloat16* Asrc[3] = { g_Ah, g_Ah, g_Al };
    const __nv_bfloat16* Bsrc[3] = { g_Bc_h, g_Bc_l, g_Bc_h };
    constexpr int TOT = 3072 / BK;

    auto load_tile = [&](int t, int buf) {
        int kg = t * BK;
        int si = kg >> 10;
        int ko = kg & 1023;
        const __nv_bfloat16* Ap = Asrc[si] + (size_t)bm * 1024 + ko;
        const __nv_bfloat16* Bp = Bsrc[si] + (size_t)ko * 160;
        const uint32_t dA = sA + buf * STG, dB = sB + buf * STG;
        #pragma unroll
        for (int i = 0; i < 2; i++) {
            int idx = tid + i * 256;
            int row = idx >> 2, c = idx & 3;
            cp16(dA + (row * LDA + c * 8) * 2, Ap + (size_t)row * 1024 + c * 8);
        }
        #pragma unroll
        for (int i = 0; i < 3; i++) {                 // 32*160/8 = 640 chunks
            int idx = tid + i * 256;
            if (idx < 640) {
                int row = idx / 20, c = idx % 20;
                cp16(dB + (row * LDB + c * 8) * 2, Bp + (size_t)row * 160 + c * 8);
            }
        }
    };

    float acc[2][N8][4];
    #pragma unroll
    for (int mt = 0; mt < 2; mt++)
        #pragma unroll
        for (int nt = 0; nt < N8; nt++)
            #pragma unroll
            for (int q = 0; q < 4; q++) acc[mt][nt][q] = 0.f;

    uint32_t aab[2], bab[NT2];
    #pragma unroll
    for (int mt = 0; mt < 2; mt++)
        aab[mt] = sA + ((wm * 32 + mt * 16 + lr) * LDA + lc8) * 2;
    #pragma unroll
    for (int nt2 = 0; nt2 < NT2; nt2++)
        bab[nt2] = sB + (lr * LDB + wn * HN + nt2 * 16 + lc8) * 2;

    #pragma unroll
    for (int p = 0; p < NST - 1; p++) { load_tile(p, p); CP_COMMIT(); }

    for (int t = 0; t < TOT; t++) {
        const int buf = t & (NST - 1);
        asm volatile("cp.async.wait_group %0;" :: "n"(NST - 2));
        __syncthreads();
        if (t + NST - 1 < TOT) load_tile(t + NST - 1, (t + NST - 1) & (NST - 1));
        CP_COMMIT();

        const uint32_t off = buf * STG;
        #pragma unroll
        for (int kk = 0; kk < BK; kk += 16) {
            uint32_t af[2][4];
            ldsm4(af[0], aab[0] + off + kk * 2);
            ldsm4(af[1], aab[1] + off + kk * 2);
            #pragma unroll
            for (int nt2 = 0; nt2 < NT2; nt2++) {
                uint32_t bf[4];
                ldsm4t(bf, bab[nt2] + off + kk * LDB * 2);
                #pragma unroll
                for (int mt = 0; mt < 2; mt++) {
                    mma_bf16(acc[mt][2 * nt2],     af[mt], bf[0], bf[1]);
                    mma_bf16(acc[mt][2 * nt2 + 1], af[mt], bf[2], bf[3]);
                }
            }
        }
    }

    // ---- epilogue: stage h_ext into smem (all cp.async already consumed) ----
    asm volatile("cp.async.wait_group 0;" ::: "memory");
    __syncthreads();
    #pragma unroll
    for (int mt = 0; mt < 2; mt++) {
        int r0 = wm * 32 + mt * 16 + (lane >> 2);
        #pragma unroll
        for (int nt = 0; nt < N8; nt++) {
            int c0 = wn * HN + nt * 8 + 2 * (lane & 3);
            hsm[r0 * LDH + c0]       = acc[mt][nt][0];
            hsm[r0 * LDH + c0 + 1]   = acc[mt][nt][1];
            hsm[(r0 + 8) * LDH + c0]     = acc[mt][nt][2];
            hsm[(r0 + 8) * LDH + c0 + 1] = acc[mt][nt][3];
        }
    }
    __syncthreads();

    // ---- fused router: 2 threads per row ----
    {
        const int r = tid >> 1, half = tid & 1;
        const int n = bm + r;
        const float* hrow = hsm + r * LDH;
        // top-2 over logits (cols 128..135); both threads compute (cheap)
        float v0 = -1e30f; int i0 = 0;
        #pragma unroll
        for (int e = 0; e < 8; e++) {
            float v = hrow[128 + e];
            if (v > v0) { v0 = v; i0 = e; }
        }
        float v1 = -1e30f; int i1 = 0;
        #pragma unroll
        for (int e = 0; e < 8; e++) {
            float v = hrow[128 + e];
            if (e != i0 && v > v1) { v1 = v; i1 = e; }
        }
        float e1v = __expf(v1 - v0);
        float p0 = 1.0f / (1.0f + e1v);
        float p1 = e1v * p0;
        if (half == 0) {
            #pragma unroll
            for (int e = 0; e < 8; e++)
                out_logits[(size_t)n * 8 + e] = hrow[128 + e];
            out_sel[(size_t)n * 2 + 0] = (float)i0;
            out_sel[(size_t)n * 2 + 1] = (float)i1;
            out_wts[(size_t)n * 2 + 0] = p0;
            out_wts[(size_t)n * 2 + 1] = p1;
        }
        const float s0 = SCALING * p0, s1 = SCALING * p1;
        const int jbase = half * 64;
        #pragma unroll
        for (int j4 = 0; j4 < 64; j4 += 4) {
            int j = jbase + j4;
            int e = j >> 4;
            float g = (e == i0) ? s0 : ((e == i1) ? s1 : 0.f);
            float4 h4 = *(const float4*)(hrow + j);
            __nv_bfloat16 h0, h1, h2, h3, l0, l1, l2, l3;
            split2(h4.x * g, h0, l0); split2(h4.y * g, h1, l1);
            split2(h4.z * g, h2, l2); split2(h4.w * g, h3, l3);
            *(uint2*)&g_Hh[(size_t)n * 128 + j] = make_uint2(pack2(h0, h1), pack2(h2, h3));
            *(uint2*)&g_Hl[(size_t)n * 128 + j] = make_uint2(pack2(l0, l1), pack2(l2, l3));
        }
    }
}

// ---------------- GEMM2 (BM=128, BN=128, BK=64, NST=3, 128 thr) -----------
// out = tokens @ W + H @ Bf ; K = 3x1024 + 3x128.
// 4 warps as 2(m) x 2(n); warp tile 64 x 64.
__global__ __launch_bounds__(128, 2) void gemm2_mma(float* __restrict__ outp) {
    constexpr int BM = 128, BN = 128, BK = 64, NST = 3;
    constexpr int LDA = BK + 8, LDB = BN + 8;
    constexpr uint32_t ASZ = BM * LDA * 2, BSZ = BK * LDB * 2;
    constexpr uint32_t STG = ASZ + BSZ;

    extern __shared__ __align__(16) char smem[];
    const uint32_t sA = s2u(smem);
    const uint32_t sB = sA + ASZ;

    const int tid = threadIdx.x, w = tid >> 5, lane = tid & 31;
    const int wm = w & 1, wn = w >> 1;
    const int lr = lane & 15, lc8 = (lane >> 4) * 8;
    const int bm = blockIdx.y * BM;
    const int bn = blockIdx.x * BN;

    const __nv_bfloat16* Asrc[6] = { g_Ah, g_Ah, g_Al, g_Hh, g_Hh, g_Hl };
    const __nv_bfloat16* Bsrc[6] = { g_Wh, g_Wl, g_Wh, g_Bf_h, g_Bf_l, g_Bf_h };
    constexpr int TOT = 3456 / BK;   // 54

    auto load_tile = [&](int t, int buf) {
        int kg = t * BK;
        int si, ko, as;
        if (kg < 3072) { si = kg >> 10; ko = kg & 1023; as = 1024; }
        else { int r = kg - 3072; si = 3 + (r >> 7); ko = r & 127; as = 128; }
        const __nv_bfloat16* Ap = Asrc[si] + (size_t)bm * as + ko;
        const __nv_bfloat16* Bp = Bsrc[si] + (size_t)ko * 1024 + bn;
        const uint32_t dA = sA + buf * STG, dB = sB + buf * STG;
        #pragma unroll
        for (int i = 0; i < 8; i++) {                 // A: 128 rows x 8 chunks
            int idx = tid + i * 128;
            int row = idx >> 3, c = idx & 7;
            cp16(dA + (row * LDA + c * 8) * 2, Ap + (size_t)row * as + c * 8);
        }
        #pragma unroll
        for (int i = 0; i < 8; i++) {                 // B: 64 rows x 16 chunks
            int idx = tid + i * 128;
            int row = idx >> 4, c = idx & 15;
            cp16(dB + (row * LDB + c * 8) * 2, Bp + (size_t)row * 1024 + c * 8);
        }
    };

    float acc[4][8][4];
    #pragma unroll
    for (int mt = 0; mt < 4; mt++)
        #pragma unroll
        for (int nt = 0; nt < 8; nt++)
            #pragma unroll
            for (int q = 0; q < 4; q++) acc[mt][nt][q] = 0.f;

    uint32_t aab[4], bab[4];
    #pragma unroll
    for (int mt = 0; mt < 4; mt++)
        aab[mt] = sA + ((wm * 64 + mt * 16 + lr) * LDA + lc8) * 2;
    #pragma unroll
    for (int nt2 = 0; nt2 < 4; nt2++)
        bab[nt2] = sB + (lr * LDB + wn * 64 + nt2 * 16 + lc8) * 2;

    #pragma unroll
    for (int p = 0; p < NST - 1; p++) { load_tile(p, p); CP_COMMIT(); }

    int buf = 0, pbuf = NST - 1;
    for (int t = 0; t < TOT; t++) {
        asm volatile("cp.async.wait_group %0;" :: "n"(NST - 2));
        __syncthreads();
        if (t + NST - 1 < TOT) load_tile(t + NST - 1, pbuf);
        CP_COMMIT();
        if (++pbuf == NST) pbuf = 0;

        const uint32_t off = buf * STG;
        if (++buf == NST) buf = 0;
        #pragma unroll
        for (int kk = 0; kk < BK; kk += 16) {
            uint32_t af[4][4];
            #pragma unroll
            for (int mt = 0; mt < 4; mt++)
                ldsm4(af[mt], aab[mt] + off + kk * 2);
            #pragma unroll
            for (int nt2 = 0; nt2 < 4; nt2++) {
                uint32_t bf[4];
                ldsm4t(bf, bab[nt2] + off + kk * LDB * 2);
                #pragma unroll
                for (int mt = 0; mt < 4; mt++) {
                    mma_bf16(acc[mt][2 * nt2],     af[mt], bf[0], bf[1]);
                    mma_bf16(acc[mt][2 * nt2 + 1], af[mt], bf[2], bf[3]);
                }
            }
        }
    }

    #pragma unroll
    for (int mt = 0; mt < 4; mt++) {
        int r0 = bm + wm * 64 + mt * 16 + (lane >> 2);
        #pragma unroll
        for (int nt = 0; nt < 8; nt++) {
            int c0 = bn + wn * 64 + nt * 8 + 2 * (lane & 3);
            *(float2*)(outp + (size_t)r0 * D_OUT + c0) =
                make_float2(acc[mt][nt][0], acc[mt][nt][1]);
            *(float2*)(outp + (size_t)(r0 + 8) * D_OUT + c0) =
                make_float2(acc[mt][nt][2], acc[mt][nt][3]);
        }
    }
}

// ---------------- Launch ----------------
extern "C" void kernel_launch(void* const* d_in, const int* in_sizes, int n_in,
                              void* d_out, int out_size) {
    const float* tokens = (const float*)d_in[0];
    const float* W_base = (const float*)d_in[1];
    const float* A      = (const float*)d_in[2];
    const float* B      = (const float*)d_in[3];
    const float* W_gate = (const float*)d_in[4];

    float* out        = (float*)d_out;
    float* out_logits = out + (size_t)N_TOK * D_OUT;
    float* out_sel    = out_logits + (size_t)N_TOK * N_EXP;
    float* out_wts    = out_sel + (size_t)N_TOK * 2;

    const int smem1 = 4 * (128 * 40 + 32 * 168) * 2;       // 83,968 B (also 128x164 fp32)
    const int smem2 = 3 * (128 * 72 + 64 * 136) * 2;       // 107,520 B

    cudaFuncSetAttribute(gemm1_mma,
                         cudaFuncAttributeMaxDynamicSharedMemorySize, smem1);
    cudaFuncSetAttribute(gemm2_mma,
                         cudaFuncAttributeMaxDynamicSharedMemorySize, smem2);

    conv_all<<<18176, 256>>>((const float4*)tokens, (const float4*)W_base,
                             A, W_gate, (const float4*)B);

    gemm1_mma<<<dim3(1, N_TOK / 128), 256, smem1>>>(out_logits, out_sel, out_wts);

    gemm2_mma<<<dim3(D_OUT / 128, N_TOK / 128), 128, smem2>>>(out);
}

// round 12
// speedup vs baseline: 1.1679x; 1.1679x over previous
#include <cuda_runtime.h>
#include <cuda_bf16.h>
#include <math.h>
#include <stdint.h>

// ---------------- Problem constants ----------------
#define N_TOK 16384
#define D_IN  1024
#define D_OUT 1024
#define N_EXP 8
#define RANK  16
#define SCALING 2.0f   // ALPHA / R

// ---------------- Device scratch ----------------
__device__ __nv_bfloat16 g_Ah[(size_t)N_TOK * D_IN];   // tokens hi   [n][k]
__device__ __nv_bfloat16 g_Al[(size_t)N_TOK * D_IN];   // tokens lo
__device__ __nv_bfloat16 g_Wh[(size_t)D_IN * D_OUT];   // W_base hi   [k][n]
__device__ __nv_bfloat16 g_Wl[(size_t)D_IN * D_OUT];
__device__ __nv_bfloat16 g_Bc_h[D_IN * 160];           // [A_flat|Wg|0] hi [k][j]
__device__ __nv_bfloat16 g_Bc_l[D_IN * 160];
__device__ __nv_bfloat16 g_Bf_h[128 * D_OUT];          // B_flat hi   [j][m]
__device__ __nv_bfloat16 g_Bf_l[128 * D_OUT];
__device__ __nv_bfloat16 g_Hh[(size_t)N_TOK * 128];    // gated H hi  [n][j]
__device__ __nv_bfloat16 g_Hl[(size_t)N_TOK * 128];

// ---------------- PTX helpers ----------------
__device__ __forceinline__ uint32_t s2u(const void* p) {
    uint32_t a;
    asm("{ .reg .u64 t; cvta.to.shared.u64 t, %1; cvt.u32.u64 %0, t; }"
        : "=r"(a) : "l"(p));
    return a;
}
__device__ __forceinline__ void cp16(uint32_t dst, const void* src) {
    asm volatile("cp.async.cg.shared.global [%0], [%1], 16;"
                 :: "r"(dst), "l"(__cvta_generic_to_global(src)));
}
#define CP_COMMIT() asm volatile("cp.async.commit_group;" ::: "memory")

__device__ __forceinline__ void ldsm4(uint32_t* r, uint32_t a) {
    asm volatile("ldmatrix.sync.aligned.m8n8.x4.shared.b16 {%0,%1,%2,%3}, [%4];"
                 : "=r"(r[0]), "=r"(r[1]), "=r"(r[2]), "=r"(r[3]) : "r"(a));
}
__device__ __forceinline__ void ldsm4t(uint32_t* r, uint32_t a) {
    asm volatile("ldmatrix.sync.aligned.m8n8.x4.trans.shared.b16 {%0,%1,%2,%3}, [%4];"
                 : "=r"(r[0]), "=r"(r[1]), "=r"(r[2]), "=r"(r[3]) : "r"(a));
}
__device__ __forceinline__ void mma_bf16(float* c, const uint32_t* a,
                                         uint32_t b0, uint32_t b1) {
    asm volatile(
        "mma.sync.aligned.m16n8k16.row.col.f32.bf16.bf16.f32 "
        "{%0,%1,%2,%3}, {%4,%5,%6,%7}, {%8,%9}, {%0,%1,%2,%3};"
        : "+f"(c[0]), "+f"(c[1]), "+f"(c[2]), "+f"(c[3])
        : "r"(a[0]), "r"(a[1]), "r"(a[2]), "r"(a[3]), "r"(b0), "r"(b1));
}

// ---------------- Conversion helpers ----------------
__device__ __forceinline__ void split2(float v, __nv_bfloat16& h, __nv_bfloat16& l) {
    h = __float2bfloat16(v);
    l = __float2bfloat16(v - __bfloat162float(h));
}
__device__ __forceinline__ uint32_t pack2(__nv_bfloat16 a, __nv_bfloat16 b) {
    return (uint32_t)__bfloat16_as_ushort(a) | ((uint32_t)__bfloat16_as_ushort(b) << 16);
}
__device__ __forceinline__ void split_store4(const float4& v, uint2* ph, uint2* pl) {
    __nv_bfloat16 h0, h1, h2, h3, l0, l1, l2, l3;
    split2(v.x, h0, l0); split2(v.y, h1, l1);
    split2(v.z, h2, l2); split2(v.w, h3, l3);
    *ph = make_uint2(pack2(h0, h1), pack2(h2, h3));
    *pl = make_uint2(pack2(l0, l1), pack2(l2, l3));
}

// ---------------- Fused conversion kernel ----------------
__global__ __launch_bounds__(256) void conv_all(
    const float4* __restrict__ tok, const float4* __restrict__ W,
    const float*  __restrict__ A,   const float* __restrict__ Wg,
    const float4* __restrict__ B) {
    const int b = blockIdx.x;
    if (b < 16384) {
        size_t i = (size_t)b * 256 + threadIdx.x;
        split_store4(tok[i], (uint2*)g_Ah + i, (uint2*)g_Al + i);
    } else if (b < 17408) {
        size_t i = (size_t)(b - 16384) * 256 + threadIdx.x;
        split_store4(W[i], (uint2*)g_Wh + i, (uint2*)g_Wl + i);
    } else if (b < 18048) {
        int i = (b - 17408) * 256 + threadIdx.x;
        if (i < 160 * 1024) {
            int d = i / 160, j = i % 160;
            float v = 0.f;
            if (j < 128) { int e = j >> 4, r = j & 15; v = A[(size_t)e * 16384 + d * 16 + r]; }
            else if (j < 136) v = Wg[(size_t)d * 8 + (j - 128)];
            __nv_bfloat16 h, l; split2(v, h, l);
            g_Bc_h[i] = h; g_Bc_l[i] = l;
        }
    } else {
        size_t i = (size_t)(b - 18048) * 256 + threadIdx.x;
        split_store4(B[i], (uint2*)g_Bf_h + i, (uint2*)g_Bf_l + i);
    }
}

// ---------------- GEMM1 + fused router ----------------
// h_ext[128,160] = tokens @ Bc ; then per-row top-2 softmax, gated H, outputs.
// BM=128, BN=160, BK=32, 256 threads, 8 warps 4(m)x2(n), warp tile 32x80.
__global__ __launch_bounds__(256, 2) void gemm1_mma(float* __restrict__ out_logits,
                                                    float* __restrict__ out_sel,
                                                    float* __restrict__ out_wts) {
    constexpr int BM = 128, BN = 160, BK = 32, NST = 4;
    constexpr int HN = BN / 2, N8 = HN / 8, NT2 = N8 / 2;   // 80, 10, 5
    constexpr int LDA = BK + 8, LDB = BN + 8;
    constexpr uint32_t ASZ = BM * LDA * 2, BSZ = BK * LDB * 2;
    constexpr uint32_t STG = ASZ + BSZ;
    constexpr int LDH = 164;    // fp32 row stride for epilogue staging

    extern __shared__ __align__(16) char smem[];
    const uint32_t sA = s2u(smem);
    const uint32_t sB = sA + ASZ;
    float* hsm = (float*)smem;  // reused at epilogue: [128][164] fp32 = 83,968 B

    const int tid = threadIdx.x, w = tid >> 5, lane = tid & 31;
    const int wm = w & 3, wn = w >> 2;
    const int lr = lane & 15, lc8 = (lane >> 4) * 8;
    const int bm = blockIdx.y * BM;

    const __nv_bfloat16* Asrc[3] = { g_Ah, g_Ah, g_Al };
    const __nv_bfloat16* Bsrc[3] = { g_Bc_h, g_Bc_l, g_Bc_h };
    constexpr int TOT = 3072 / BK;

    auto load_tile = [&](int t, int buf) {
        int kg = t * BK;
        int si = kg >> 10;
        int ko = kg & 1023;
        const __nv_bfloat16* Ap = Asrc[si] + (size_t)bm * 1024 + ko;
        const __nv_bfloat16* Bp = Bsrc[si] + (size_t)ko * 160;
        const uint32_t dA = sA + buf * STG, dB = sB + buf * STG;
        #pragma unroll
        for (int i = 0; i < 2; i++) {
            int idx = tid + i * 256;
            int row = idx >> 2, c = idx & 3;
            cp16(dA + (row * LDA + c * 8) * 2, Ap + (size_t)row * 1024 + c * 8);
        }
        #pragma unroll
        for (int i = 0; i < 3; i++) {                 // 32*160/8 = 640 chunks
            int idx = tid + i * 256;
            if (idx < 640) {
                int row = idx / 20, c = idx % 20;
                cp16(dB + (row * LDB + c * 8) * 2, Bp + (size_t)row * 160 + c * 8);
            }
        }
    };

    float acc[2][N8][4];
    #pragma unroll
    for (int mt = 0; mt < 2; mt++)
        #pragma unroll
        for (int nt = 0; nt < N8; nt++)
            #pragma unroll
            for (int q = 0; q < 4; q++) acc[mt][nt][q] = 0.f;

    uint32_t aab[2], bab[NT2];
    #pragma unroll
    for (int mt = 0; mt < 2; mt++)
        aab[mt] = sA + ((wm * 32 + mt * 16 + lr) * LDA + lc8) * 2;
    #pragma unroll
    for (int nt2 = 0; nt2 < NT2; nt2++)
        bab[nt2] = sB + (lr * LDB + wn * HN + nt2 * 16 + lc8) * 2;

    #pragma unroll
    for (int p = 0; p < NST - 1; p++) { load_tile(p, p); CP_COMMIT(); }

    for (int t = 0; t < TOT; t++) {
        const int buf = t & (NST - 1);
        asm volatile("cp.async.wait_group %0;" :: "n"(NST - 2));
        __syncthreads();
        if (t + NST - 1 < TOT) load_tile(t + NST - 1, (t + NST - 1) & (NST - 1));
        CP_COMMIT();

        const uint32_t off = buf * STG;
        #pragma unroll
        for (int kk = 0; kk < BK; kk += 16) {
            uint32_t af[2][4];
            ldsm4(af[0], aab[0] + off + kk * 2);
            ldsm4(af[1], aab[1] + off + kk * 2);
            #pragma unroll
            for (int nt2 = 0; nt2 < NT2; nt2++) {
                uint32_t bf[4];
                ldsm4t(bf, bab[nt2] + off + kk * LDB * 2);
                #pragma unroll
                for (int mt = 0; mt < 2; mt++) {
                    mma_bf16(acc[mt][2 * nt2],     af[mt], bf[0], bf[1]);
                    mma_bf16(acc[mt][2 * nt2 + 1], af[mt], bf[2], bf[3]);
                }
            }
        }
    }

    // ---- epilogue: stage h_ext into smem (all cp.async already consumed) ----
    asm volatile("cp.async.wait_group 0;" ::: "memory");
    __syncthreads();
    #pragma unroll
    for (int mt = 0; mt < 2; mt++) {
        int r0 = wm * 32 + mt * 16 + (lane >> 2);
        #pragma unroll
        for (int nt = 0; nt < N8; nt++) {
            int c0 = wn * HN + nt * 8 + 2 * (lane & 3);
            hsm[r0 * LDH + c0]       = acc[mt][nt][0];
            hsm[r0 * LDH + c0 + 1]   = acc[mt][nt][1];
            hsm[(r0 + 8) * LDH + c0]     = acc[mt][nt][2];
            hsm[(r0 + 8) * LDH + c0 + 1] = acc[mt][nt][3];
        }
    }
    __syncthreads();

    // ---- fused router: 2 threads per row ----
    {
        const int r = tid >> 1, half = tid & 1;
        const int n = bm + r;
        const float* hrow = hsm + r * LDH;
        float v0 = -1e30f; int i0 = 0;
        #pragma unroll
        for (int e = 0; e < 8; e++) {
            float v = hrow[128 + e];
            if (v > v0) { v0 = v; i0 = e; }
        }
        float v1 = -1e30f; int i1 = 0;
        #pragma unroll
        for (int e = 0; e < 8; e++) {
            float v = hrow[128 + e];
            if (e != i0 && v > v1) { v1 = v; i1 = e; }
        }
        float e1v = __expf(v1 - v0);
        float p0 = 1.0f / (1.0f + e1v);
        float p1 = e1v * p0;
        if (half == 0) {
            #pragma unroll
            for (int e = 0; e < 8; e++)
                out_logits[(size_t)n * 8 + e] = hrow[128 + e];
            out_sel[(size_t)n * 2 + 0] = (float)i0;
            out_sel[(size_t)n * 2 + 1] = (float)i1;
            out_wts[(size_t)n * 2 + 0] = p0;
            out_wts[(size_t)n * 2 + 1] = p1;
        }
        const float s0 = SCALING * p0, s1 = SCALING * p1;
        const int jbase = half * 64;
        #pragma unroll
        for (int j4 = 0; j4 < 64; j4 += 4) {
            int j = jbase + j4;
            int e = j >> 4;
            float g = (e == i0) ? s0 : ((e == i1) ? s1 : 0.f);
            float4 h4 = *(const float4*)(hrow + j);
            __nv_bfloat16 h0, h1, h2, h3, l0, l1, l2, l3;
            split2(h4.x * g, h0, l0); split2(h4.y * g, h1, l1);
            split2(h4.z * g, h2, l2); split2(h4.w * g, h3, l3);
            *(uint2*)&g_Hh[(size_t)n * 128 + j] = make_uint2(pack2(h0, h1), pack2(h2, h3));
            *(uint2*)&g_Hl[(size_t)n * 128 + j] = make_uint2(pack2(l0, l1), pack2(l2, l3));
        }
    }
}

// ---------------- GEMM2 (BM=128, BN=128, BK=32, NST=5, 128 thr) -----------
// out = tokens @ W + H @ Bf ; K = 3x1024 + 3x128.
// 4 warps as 2(m) x 2(n); warp tile 64 x 64.  (R10-proven config)
__global__ __launch_bounds__(128, 2) void gemm2_mma(float* __restrict__ outp) {
    constexpr int BM = 128, BN = 128, BK = 32, NST = 5;
    constexpr int LDA = BK + 8, LDB = BN + 8;
    constexpr uint32_t ASZ = BM * LDA * 2, BSZ = BK * LDB * 2;
    constexpr uint32_t STG = ASZ + BSZ;

    extern __shared__ __align__(16) char smem[];
    const uint32_t sA = s2u(smem);
    const uint32_t sB = sA + ASZ;

    const int tid = threadIdx.x, w = tid >> 5, lane = tid & 31;
    const int wm = w & 1, wn = w >> 1;
    const int lr = lane & 15, lc8 = (lane >> 4) * 8;
    const int bm = blockIdx.y * BM;
    const int bn = blockIdx.x * BN;

    const __nv_bfloat16* Asrc[6] = { g_Ah, g_Ah, g_Al, g_Hh, g_Hh, g_Hl };
    const __nv_bfloat16* Bsrc[6] = { g_Wh, g_Wl, g_Wh, g_Bf_h, g_Bf_l, g_Bf_h };
    constexpr int TOT = 3456 / BK;   // 108

    auto load_tile = [&](int t, int buf) {
        int kg = t * BK;
        int si, ko, as;
        if (kg < 3072) { si = kg >> 10; ko = kg & 1023; as = 1024; }
        else { int r = kg - 3072; si = 3 + (r >> 7); ko = r & 127; as = 128; }
        const __nv_bfloat16* Ap = Asrc[si] + (size_t)bm * as + ko;
        const __nv_bfloat16* Bp = Bsrc[si] + (size_t)ko * 1024 + bn;
        const uint32_t dA = sA + buf * STG, dB = sB + buf * STG;
        #pragma unroll
        for (int i = 0; i < 4; i++) {                 // A: 512 cp16
            int idx = tid + i * 128;
            int row = idx >> 2, c = idx & 3;
            cp16(dA + (row * LDA + c * 8) * 2, Ap + (size_t)row * as + c * 8);
        }
        #pragma unroll
        for (int i = 0; i < 4; i++) {                 // B: 512 cp16
            int idx = tid + i * 128;
            int row = idx >> 4, c = idx & 15;
            cp16(dB + (row * LDB + c * 8) * 2, Bp + (size_t)row * 1024 + c * 8);
        }
    };

    float acc[4][8][4];
    #pragma unroll
    for (int mt = 0; mt < 4; mt++)
        #pragma unroll
        for (int nt = 0; nt < 8; nt++)
            #pragma unroll
            for (int q = 0; q < 4; q++) acc[mt][nt][q] = 0.f;

    uint32_t aab[4], bab[4];
    #pragma unroll
    for (int mt = 0; mt < 4; mt++)
        aab[mt] = sA + ((wm * 64 + mt * 16 + lr) * LDA + lc8) * 2;
    #pragma unroll
    for (int nt2 = 0; nt2 < 4; nt2++)
        bab[nt2] = sB + (lr * LDB + wn * 64 + nt2 * 16 + lc8) * 2;

    #pragma unroll
    for (int p = 0; p < NST - 1; p++) { load_tile(p, p); CP_COMMIT(); }

    int buf = 0, pbuf = NST - 1;
    for (int t = 0; t < TOT; t++) {
        asm volatile("cp.async.wait_group %0;" :: "n"(NST - 2));
        __syncthreads();
        if (t + NST - 1 < TOT) load_tile(t + NST - 1, pbuf);
        CP_COMMIT();
        if (++pbuf == NST) pbuf = 0;

        const uint32_t off = buf * STG;
        if (++buf == NST) buf = 0;
        #pragma unroll
        for (int kk = 0; kk < BK; kk += 16) {
            uint32_t af[4][4];
            #pragma unroll
            for (int mt = 0; mt < 4; mt++)
                ldsm4(af[mt], aab[mt] + off + kk * 2);
            #pragma unroll
            for (int nt2 = 0; nt2 < 4; nt2++) {
                uint32_t bf[4];
                ldsm4t(bf, bab[nt2] + off + kk * LDB * 2);
                #pragma unroll
                for (int mt = 0; mt < 4; mt++) {
                    mma_bf16(acc[mt][2 * nt2],     af[mt], bf[0], bf[1]);
                    mma_bf16(acc[mt][2 * nt2 + 1], af[mt], bf[2], bf[3]);
                }
            }
        }
    }

    #pragma unroll
    for (int mt = 0; mt < 4; mt++) {
        int r0 = bm + wm * 64 + mt * 16 + (lane >> 2);
        #pragma unroll
        for (int nt = 0; nt < 8; nt++) {
            int c0 = bn + wn * 64 + nt * 8 + 2 * (lane & 3);
            *(float2*)(outp + (size_t)r0 * D_OUT + c0) =
                make_float2(acc[mt][nt][0], acc[mt][nt][1]);
            *(float2*)(outp + (size_t)(r0 + 8) * D_OUT + c0) =
                make_float2(acc[mt][nt][2], acc[mt][nt][3]);
        }
    }
}

// ---------------- Launch ----------------
extern "C" void kernel_launch(void* const* d_in, const int* in_sizes, int n_in,
                              void* d_out, int out_size) {
    const float* tokens = (const float*)d_in[0];
    const float* W_base = (const float*)d_in[1];
    const float* A      = (const float*)d_in[2];
    const float* B      = (const float*)d_in[3];
    const float* W_gate = (const float*)d_in[4];

    float* out        = (float*)d_out;
    float* out_logits = out + (size_t)N_TOK * D_OUT;
    float* out_sel    = out_logits + (size_t)N_TOK * N_EXP;
    float* out_wts    = out_sel + (size_t)N_TOK * 2;

    const int smem1 = 4 * (128 * 40 + 32 * 168) * 2;       // 83,968 B (also 128x164 fp32)
    const int smem2 = 5 * (128 * 40 + 32 * 136) * 2;       // 94,720 B

    cudaFuncSetAttribute(gemm1_mma,
                         cudaFuncAttributeMaxDynamicSharedMemorySize, smem1);
    cudaFuncSetAttribute(gemm2_mma,
                         cudaFuncAttributeMaxDynamicSharedMemorySize, smem2);

    conv_all<<<18176, 256>>>((const float4*)tokens, (const float4*)W_base,
                             A, W_gate, (const float4*)B);

    gemm1_mma<<<dim3(1, N_TOK / 128), 256, smem1>>>(out_logits, out_sel, out_wts);

    gemm2_mma<<<dim3(D_OUT / 128, N_TOK / 128), 128, smem2>>>(out);
}

// round 13
// speedup vs baseline: 1.1806x; 1.0109x over previous
#include <cuda_runtime.h>
#include <cuda_bf16.h>
#include <math.h>
#include <stdint.h>

// ---------------- Problem constants ----------------
#define N_TOK 16384
#define D_IN  1024
#define D_OUT 1024
#define N_EXP 8
#define RANK  16
#define SCALING 2.0f   // ALPHA / R

// ---------------- Device scratch ----------------
__device__ __nv_bfloat16 g_Ah[(size_t)N_TOK * D_IN];   // tokens hi   [n][k]
__device__ __nv_bfloat16 g_Al[(size_t)N_TOK * D_IN];   // tokens lo
__device__ __nv_bfloat16 g_Wh[(size_t)D_IN * D_OUT];   // W_base hi   [k][n]
__device__ __nv_bfloat16 g_Wl[(size_t)D_IN * D_OUT];
__device__ __nv_bfloat16 g_Bc_h[D_IN * 160];           // [A_flat|Wg|0] hi [k][j]
__device__ __nv_bfloat16 g_Bc_l[D_IN * 160];
__device__ __nv_bfloat16 g_Bf_h[128 * D_OUT];          // B_flat hi   [j][m]
__device__ __nv_bfloat16 g_Bf_l[128 * D_OUT];
__device__ __nv_bfloat16 g_Hh[(size_t)N_TOK * 128];    // gated H hi  [n][j]
__device__ __nv_bfloat16 g_Hl[(size_t)N_TOK * 128];

// ---------------- PTX helpers ----------------
__device__ __forceinline__ uint32_t s2u(const void* p) {
    uint32_t a;
    asm("{ .reg .u64 t; cvta.to.shared.u64 t, %1; cvt.u32.u64 %0, t; }"
        : "=r"(a) : "l"(p));
    return a;
}
__device__ __forceinline__ void cp16(uint32_t dst, const void* src) {
    asm volatile("cp.async.cg.shared.global [%0], [%1], 16;"
                 :: "r"(dst), "l"(__cvta_generic_to_global(src)));
}
#define CP_COMMIT() asm volatile("cp.async.commit_group;" ::: "memory")

__device__ __forceinline__ void ldsm4(uint32_t* r, uint32_t a) {
    asm volatile("ldmatrix.sync.aligned.m8n8.x4.shared.b16 {%0,%1,%2,%3}, [%4];"
                 : "=r"(r[0]), "=r"(r[1]), "=r"(r[2]), "=r"(r[3]) : "r"(a));
}
__device__ __forceinline__ void ldsm4t(uint32_t* r, uint32_t a) {
    asm volatile("ldmatrix.sync.aligned.m8n8.x4.trans.shared.b16 {%0,%1,%2,%3}, [%4];"
                 : "=r"(r[0]), "=r"(r[1]), "=r"(r[2]), "=r"(r[3]) : "r"(a));
}
__device__ __forceinline__ void mma_bf16(float* c, const uint32_t* a,
                                         uint32_t b0, uint32_t b1) {
    asm volatile(
        "mma.sync.aligned.m16n8k16.row.col.f32.bf16.bf16.f32 "
        "{%0,%1,%2,%3}, {%4,%5,%6,%7}, {%8,%9}, {%0,%1,%2,%3};"
        : "+f"(c[0]), "+f"(c[1]), "+f"(c[2]), "+f"(c[3])
        : "r"(a[0]), "r"(a[1]), "r"(a[2]), "r"(a[3]), "r"(b0), "r"(b1));
}

// ---------------- Conversion helpers ----------------
__device__ __forceinline__ void split2(float v, __nv_bfloat16& h, __nv_bfloat16& l) {
    h = __float2bfloat16(v);
    l = __float2bfloat16(v - __bfloat162float(h));
}
__device__ __forceinline__ uint32_t pack2(__nv_bfloat16 a, __nv_bfloat16 b) {
    return (uint32_t)__bfloat16_as_ushort(a) | ((uint32_t)__bfloat16_as_ushort(b) << 16);
}
__device__ __forceinline__ void split_store4(const float4& v, uint2* ph, uint2* pl) {
    __nv_bfloat16 h0, h1, h2, h3, l0, l1, l2, l3;
    split2(v.x, h0, l0); split2(v.y, h1, l1);
    split2(v.z, h2, l2); split2(v.w, h3, l3);
    *ph = make_uint2(pack2(h0, h1), pack2(h2, h3));
    *pl = make_uint2(pack2(l0, l1), pack2(l2, l3));
}

// ---------------- Fused conversion kernel ----------------
__global__ __launch_bounds__(256) void conv_all(
    const float4* __restrict__ tok, const float4* __restrict__ W,
    const float*  __restrict__ A,   const float* __restrict__ Wg,
    const float4* __restrict__ B) {
    const int b = blockIdx.x;
    if (b < 16384) {
        size_t i = (size_t)b * 256 + threadIdx.x;
        split_store4(tok[i], (uint2*)g_Ah + i, (uint2*)g_Al + i);
    } else if (b < 17408) {
        size_t i = (size_t)(b - 16384) * 256 + threadIdx.x;
        split_store4(W[i], (uint2*)g_Wh + i, (uint2*)g_Wl + i);
    } else if (b < 18048) {
        int i = (b - 17408) * 256 + threadIdx.x;
        if (i < 160 * 1024) {
            int d = i / 160, j = i % 160;
            float v = 0.f;
            if (j < 128) { int e = j >> 4, r = j & 15; v = A[(size_t)e * 16384 + d * 16 + r]; }
            else if (j < 136) v = Wg[(size_t)d * 8 + (j - 128)];
            __nv_bfloat16 h, l; split2(v, h, l);
            g_Bc_h[i] = h; g_Bc_l[i] = l;
        }
    } else {
        size_t i = (size_t)(b - 18048) * 256 + threadIdx.x;
        split_store4(B[i], (uint2*)g_Bf_h + i, (uint2*)g_Bf_l + i);
    }
}

// ---------------- GEMM1 + fused router (BM=64 for 2 CTAs/SM) ----------
// h_ext[64,160] = tokens @ Bc ; then per-row top-2 softmax, gated H, outputs.
// BM=64, BN=160, BK=32, 256 threads, 8 warps 4(m)x2(n), warp tile 16x80.
__global__ __launch_bounds__(256, 2) void gemm1_mma(float* __restrict__ out_logits,
                                                    float* __restrict__ out_sel,
                                                    float* __restrict__ out_wts) {
    constexpr int BM = 64, BN = 160, BK = 32, NST = 4;
    constexpr int HN = BN / 2, N8 = HN / 8, NT2 = N8 / 2;   // 80, 10, 5
    constexpr int LDA = BK + 8, LDB = BN + 8;
    constexpr uint32_t ASZ = BM * LDA * 2, BSZ = BK * LDB * 2;   // 5120, 10752
    constexpr uint32_t STG = ASZ + BSZ;                          // 15872
    constexpr int LDH = 164;    // fp32 row stride for epilogue staging

    extern __shared__ __align__(16) char smem[];
    const uint32_t sA = s2u(smem);
    const uint32_t sB = sA + ASZ;
    float* hsm = (float*)smem;  // epilogue reuse: [64][164] fp32 = 41,984 B

    const int tid = threadIdx.x, w = tid >> 5, lane = tid & 31;
    const int wm = w & 3, wn = w >> 2;
    const int lr = lane & 15, lc8 = (lane >> 4) * 8;
    const int bm = blockIdx.y * BM;

    const __nv_bfloat16* Asrc[3] = { g_Ah, g_Ah, g_Al };
    const __nv_bfloat16* Bsrc[3] = { g_Bc_h, g_Bc_l, g_Bc_h };
    constexpr int TOT = 3072 / BK;   // 96

    auto load_tile = [&](int t, int buf) {
        int kg = t * BK;
        int si = kg >> 10;
        int ko = kg & 1023;
        const __nv_bfloat16* Ap = Asrc[si] + (size_t)bm * 1024 + ko;
        const __nv_bfloat16* Bp = Bsrc[si] + (size_t)ko * 160;
        const uint32_t dA = sA + buf * STG, dB = sB + buf * STG;
        {   // A: 64 rows x 4 chunks = 256 cp16
            int row = tid >> 2, c = tid & 3;
            cp16(dA + (row * LDA + c * 8) * 2, Ap + (size_t)row * 1024 + c * 8);
        }
        #pragma unroll
        for (int i = 0; i < 3; i++) {                 // B: 32*160/8 = 640 chunks
            int idx = tid + i * 256;
            if (idx < 640) {
                int row = idx / 20, c = idx % 20;
                cp16(dB + (row * LDB + c * 8) * 2, Bp + (size_t)row * 160 + c * 8);
            }
        }
    };

    float acc[N8][4];
    #pragma unroll
    for (int nt = 0; nt < N8; nt++)
        #pragma unroll
        for (int q = 0; q < 4; q++) acc[nt][q] = 0.f;

    const uint32_t aab = sA + ((wm * 16 + lr) * LDA + lc8) * 2;
    uint32_t bab[NT2];
    #pragma unroll
    for (int nt2 = 0; nt2 < NT2; nt2++)
        bab[nt2] = sB + (lr * LDB + wn * HN + nt2 * 16 + lc8) * 2;

    #pragma unroll
    for (int p = 0; p < NST - 1; p++) { load_tile(p, p); CP_COMMIT(); }

    for (int t = 0; t < TOT; t++) {
        const int buf = t & (NST - 1);
        asm volatile("cp.async.wait_group %0;" :: "n"(NST - 2));
        __syncthreads();
        if (t + NST - 1 < TOT) load_tile(t + NST - 1, (t + NST - 1) & (NST - 1));
        CP_COMMIT();

        const uint32_t off = buf * STG;
        #pragma unroll
        for (int kk = 0; kk < BK; kk += 16) {
            uint32_t af[4];
            ldsm4(af, aab + off + kk * 2);
            #pragma unroll
            for (int nt2 = 0; nt2 < NT2; nt2++) {
                uint32_t bf[4];
                ldsm4t(bf, bab[nt2] + off + kk * LDB * 2);
                mma_bf16(acc[2 * nt2],     af, bf[0], bf[1]);
                mma_bf16(acc[2 * nt2 + 1], af, bf[2], bf[3]);
            }
        }
    }

    // ---- epilogue: stage h_ext into smem ----
    asm volatile("cp.async.wait_group 0;" ::: "memory");
    __syncthreads();
    {
        int r0 = wm * 16 + (lane >> 2);
        #pragma unroll
        for (int nt = 0; nt < N8; nt++) {
            int c0 = wn * HN + nt * 8 + 2 * (lane & 3);
            hsm[r0 * LDH + c0]           = acc[nt][0];
            hsm[r0 * LDH + c0 + 1]       = acc[nt][1];
            hsm[(r0 + 8) * LDH + c0]     = acc[nt][2];
            hsm[(r0 + 8) * LDH + c0 + 1] = acc[nt][3];
        }
    }
    __syncthreads();

    // ---- fused router: 4 threads per row (64 rows) ----
    {
        const int r = tid >> 2, q = tid & 3;
        const int n = bm + r;
        const float* hrow = hsm + r * LDH;
        float v0 = -1e30f; int i0 = 0;
        #pragma unroll
        for (int e = 0; e < 8; e++) {
            float v = hrow[128 + e];
            if (v > v0) { v0 = v; i0 = e; }
        }
        float v1 = -1e30f; int i1 = 0;
        #pragma unroll
        for (int e = 0; e < 8; e++) {
            float v = hrow[128 + e];
            if (e != i0 && v > v1) { v1 = v; i1 = e; }
        }
        float e1v = __expf(v1 - v0);
        float p0 = 1.0f / (1.0f + e1v);
        float p1 = e1v * p0;
        if (q == 0) {
            #pragma unroll
            for (int e = 0; e < 8; e++)
                out_logits[(size_t)n * 8 + e] = hrow[128 + e];
            out_sel[(size_t)n * 2 + 0] = (float)i0;
            out_sel[(size_t)n * 2 + 1] = (float)i1;
            out_wts[(size_t)n * 2 + 0] = p0;
            out_wts[(size_t)n * 2 + 1] = p1;
        }
        const float s0 = SCALING * p0, s1 = SCALING * p1;
        const int jbase = q * 32;
        #pragma unroll
        for (int j4 = 0; j4 < 32; j4 += 4) {
            int j = jbase + j4;
            int e = j >> 4;
            float g = (e == i0) ? s0 : ((e == i1) ? s1 : 0.f);
            float4 h4 = *(const float4*)(hrow + j);
            __nv_bfloat16 h0, h1, h2, h3, l0, l1, l2, l3;
            split2(h4.x * g, h0, l0); split2(h4.y * g, h1, l1);
            split2(h4.z * g, h2, l2); split2(h4.w * g, h3, l3);
            *(uint2*)&g_Hh[(size_t)n * 128 + j] = make_uint2(pack2(h0, h1), pack2(h2, h3));
            *(uint2*)&g_Hl[(size_t)n * 128 + j] = make_uint2(pack2(l0, l1), pack2(l2, l3));
        }
    }
}

// ---------------- GEMM2 (BM=128, BN=128, BK=32, NST=5, 128 thr) -----------
// out = tokens @ W + H @ Bf ; K = 3x1024 + 3x128.
// 4 warps as 2(m) x 2(n); warp tile 64 x 64.  (R10-proven config)
__global__ __launch_bounds__(128, 2) void gemm2_mma(float* __restrict__ outp) {
    constexpr int BM = 128, BN = 128, BK = 32, NST = 5;
    constexpr int LDA = BK + 8, LDB = BN + 8;
    constexpr uint32_t ASZ = BM * LDA * 2, BSZ = BK * LDB * 2;
    constexpr uint32_t STG = ASZ + BSZ;

    extern __shared__ __align__(16) char smem[];
    const uint32_t sA = s2u(smem);
    const uint32_t sB = sA + ASZ;

    const int tid = threadIdx.x, w = tid >> 5, lane = tid & 31;
    const int wm = w & 1, wn = w >> 1;
    const int lr = lane & 15, lc8 = (lane >> 4) * 8;
    const int bm = blockIdx.y * BM;
    const int bn = blockIdx.x * BN;

    const __nv_bfloat16* Asrc[6] = { g_Ah, g_Ah, g_Al, g_Hh, g_Hh, g_Hl };
    const __nv_bfloat16* Bsrc[6] = { g_Wh, g_Wl, g_Wh, g_Bf_h, g_Bf_l, g_Bf_h };
    constexpr int TOT = 3456 / BK;   // 108

    auto load_tile = [&](int t, int buf) {
        int kg = t * BK;
        int si, ko, as;
        if (kg < 3072) { si = kg >> 10; ko = kg & 1023; as = 1024; }
        else { int r = kg - 3072; si = 3 + (r >> 7); ko = r & 127; as = 128; }
        const __nv_bfloat16* Ap = Asrc[si] + (size_t)bm * as + ko;
        const __nv_bfloat16* Bp = Bsrc[si] + (size_t)ko * 1024 + bn;
        const uint32_t dA = sA + buf * STG, dB = sB + buf * STG;
        #pragma unroll
        for (int i = 0; i < 4; i++) {                 // A: 512 cp16
            int idx = tid + i * 128;
            int row = idx >> 2, c = idx & 3;
            cp16(dA + (row * LDA + c * 8) * 2, Ap + (size_t)row * as + c * 8);
        }
        #pragma unroll
        for (int i = 0; i < 4; i++) {                 // B: 512 cp16
            int idx = tid + i * 128;
            int row = idx >> 4, c = idx & 15;
            cp16(dB + (row * LDB + c * 8) * 2, Bp + (size_t)row * 1024 + c * 8);
        }
    };

    float acc[4][8][4];
    #pragma unroll
    for (int mt = 0; mt < 4; mt++)
        #pragma unroll
        for (int nt = 0; nt < 8; nt++)
            #pragma unroll
            for (int q = 0; q < 4; q++) acc[mt][nt][q] = 0.f;

    uint32_t aab[4], bab[4];
    #pragma unroll
    for (int mt = 0; mt < 4; mt++)
        aab[mt] = sA + ((wm * 64 + mt * 16 + lr) * LDA + lc8) * 2;
    #pragma unroll
    for (int nt2 = 0; nt2 < 4; nt2++)
        bab[nt2] = sB + (lr * LDB + wn * 64 + nt2 * 16 + lc8) * 2;

    #pragma unroll
    for (int p = 0; p < NST - 1; p++) { load_tile(p, p); CP_COMMIT(); }

    int buf = 0, pbuf = NST - 1;
    for (int t = 0; t < TOT; t++) {
        asm volatile("cp.async.wait_group %0;" :: "n"(NST - 2));
        __syncthreads();
        if (t + NST - 1 < TOT) load_tile(t + NST - 1, pbuf);
        CP_COMMIT();
        if (++pbuf == NST) pbuf = 0;

        const uint32_t off = buf * STG;
        if (++buf == NST) buf = 0;
        #pragma unroll
        for (int kk = 0; kk < BK; kk += 16) {
            uint32_t af[4][4];
            #pragma unroll
            for (int mt = 0; mt < 4; mt++)
                ldsm4(af[mt], aab[mt] + off + kk * 2);
            #pragma unroll
            for (int nt2 = 0; nt2 < 4; nt2++) {
                uint32_t bf[4];
                ldsm4t(bf, bab[nt2] + off + kk * LDB * 2);
                #pragma unroll
                for (int mt = 0; mt < 4; mt++) {
                    mma_bf16(acc[mt][2 * nt2],     af[mt], bf[0], bf[1]);
                    mma_bf16(acc[mt][2 * nt2 + 1], af[mt], bf[2], bf[3]);
                }
            }
        }
    }

    #pragma unroll
    for (int mt = 0; mt < 4; mt++) {
        int r0 = bm + wm * 64 + mt * 16 + (lane >> 2);
        #pragma unroll
        for (int nt = 0; nt < 8; nt++) {
            int c0 = bn + wn * 64 + nt * 8 + 2 * (lane & 3);
            *(float2*)(outp + (size_t)r0 * D_OUT + c0) =
                make_float2(acc[mt][nt][0], acc[mt][nt][1]);
            *(float2*)(outp + (size_t)(r0 + 8) * D_OUT + c0) =
                make_float2(acc[mt][nt][2], acc[mt][nt][3]);
        }
    }
}

// ---------------- Launch ----------------
extern "C" void kernel_launch(void* const* d_in, const int* in_sizes, int n_in,
                              void* d_out, int out_size) {
    const float* tokens = (const float*)d_in[0];
    const float* W_base = (const float*)d_in[1];
    const float* A      = (const float*)d_in[2];
    const float* B      = (const float*)d_in[3];
    const float* W_gate = (const float*)d_in[4];

    float* out        = (float*)d_out;
    float* out_logits = out + (size_t)N_TOK * D_OUT;
    float* out_sel    = out_logits + (size_t)N_TOK * N_EXP;
    float* out_wts    = out_sel + (size_t)N_TOK * 2;

    const int smem1 = 4 * (64 * 40 + 32 * 168) * 2;        // 63,488 B
    const int smem2 = 5 * (128 * 40 + 32 * 136) * 2;       // 94,720 B

    cudaFuncSetAttribute(gemm1_mma,
                         cudaFuncAttributeMaxDynamicSharedMemorySize, smem1);
    cudaFuncSetAttribute(gemm2_mma,
                         cudaFuncAttributeMaxDynamicSharedMemorySize, smem2);

    conv_all<<<18176, 256>>>((const float4*)tokens, (const float4*)W_base,
                             A, W_gate, (const float4*)B);

    gemm1_mma<<<dim3(1, N_TOK / 64), 256, smem1>>>(out_logits, out_sel, out_wts);

    gemm2_mma<<<dim3(D_OUT / 128, N_TOK / 128), 128, smem2>>>(out);
}

// round 14
// speedup vs baseline: 1.2476x; 1.0568x over previous
#include <cuda_runtime.h>
#include <cuda_bf16.h>
#include <math.h>
#include <stdint.h>

// ---------------- Problem constants ----------------
#define N_TOK 16384
#define D_IN  1024
#define D_OUT 1024
#define N_EXP 8
#define RANK  16
#define SCALING 2.0f   // ALPHA / R

// ---------------- Device scratch ----------------
__device__ __nv_bfloat16 g_Ah[(size_t)N_TOK * D_IN];   // tokens hi   [n][k]
__device__ __nv_bfloat16 g_Al[(size_t)N_TOK * D_IN];   // tokens lo
__device__ __nv_bfloat16 g_Wh[(size_t)D_IN * D_OUT];   // W_base hi   [k][n]
__device__ __nv_bfloat16 g_Wl[(size_t)D_IN * D_OUT];
__device__ __nv_bfloat16 g_Bc_h[D_IN * 160];           // [A_flat|Wg|0] hi [k][j]
__device__ __nv_bfloat16 g_Bc_l[D_IN * 160];
__device__ __nv_bfloat16 g_Bf_h[128 * D_OUT];          // B_flat hi   [j][m]
__device__ __nv_bfloat16 g_Bf_l[128 * D_OUT];
__device__ __nv_bfloat16 g_Hh[(size_t)N_TOK * 128];    // gated H hi  [n][j]
__device__ __nv_bfloat16 g_Hl[(size_t)N_TOK * 128];

// ---------------- PTX helpers ----------------
__device__ __forceinline__ uint32_t s2u(const void* p) {
    uint32_t a;
    asm("{ .reg .u64 t; cvta.to.shared.u64 t, %1; cvt.u32.u64 %0, t; }"
        : "=r"(a) : "l"(p));
    return a;
}
__device__ __forceinline__ void cp16(uint32_t dst, const void* src) {
    asm volatile("cp.async.cg.shared.global [%0], [%1], 16;"
                 :: "r"(dst), "l"(__cvta_generic_to_global(src)));
}
#define CP_COMMIT() asm volatile("cp.async.commit_group;" ::: "memory")

__device__ __forceinline__ void ldsm4(uint32_t* r, uint32_t a) {
    asm volatile("ldmatrix.sync.aligned.m8n8.x4.shared.b16 {%0,%1,%2,%3}, [%4];"
                 : "=r"(r[0]), "=r"(r[1]), "=r"(r[2]), "=r"(r[3]) : "r"(a));
}
__device__ __forceinline__ void ldsm4t(uint32_t* r, uint32_t a) {
    asm volatile("ldmatrix.sync.aligned.m8n8.x4.trans.shared.b16 {%0,%1,%2,%3}, [%4];"
                 : "=r"(r[0]), "=r"(r[1]), "=r"(r[2]), "=r"(r[3]) : "r"(a));
}
__device__ __forceinline__ void mma_bf16(float* c, const uint32_t* a,
                                         uint32_t b0, uint32_t b1) {
    asm volatile(
        "mma.sync.aligned.m16n8k16.row.col.f32.bf16.bf16.f32 "
        "{%0,%1,%2,%3}, {%4,%5,%6,%7}, {%8,%9}, {%0,%1,%2,%3};"
        : "+f"(c[0]), "+f"(c[1]), "+f"(c[2]), "+f"(c[3])
        : "r"(a[0]), "r"(a[1]), "r"(a[2]), "r"(a[3]), "r"(b0), "r"(b1));
}

// ---------------- Conversion helpers ----------------
__device__ __forceinline__ void split2(float v, __nv_bfloat16& h, __nv_bfloat16& l) {
    h = __float2bfloat16(v);
    l = __float2bfloat16(v - __bfloat162float(h));
}
__device__ __forceinline__ uint32_t pack2(__nv_bfloat16 a, __nv_bfloat16 b) {
    return (uint32_t)__bfloat16_as_ushort(a) | ((uint32_t)__bfloat16_as_ushort(b) << 16);
}
__device__ __forceinline__ void split_store4(const float4& v, uint2* ph, uint2* pl) {
    __nv_bfloat16 h0, h1, h2, h3, l0, l1, l2, l3;
    split2(v.x, h0, l0); split2(v.y, h1, l1);
    split2(v.z, h2, l2); split2(v.w, h3, l3);
    *ph = make_uint2(pack2(h0, h1), pack2(h2, h3));
    *pl = make_uint2(pack2(l0, l1), pack2(l2, l3));
}

// ---------------- Fused conversion kernel ----------------
__global__ __launch_bounds__(256) void conv_all(
    const float4* __restrict__ tok, const float4* __restrict__ W,
    const float*  __restrict__ A,   const float* __restrict__ Wg,
    const float4* __restrict__ B) {
    const int b = blockIdx.x;
    if (b < 16384) {
        size_t i = (size_t)b * 256 + threadIdx.x;
        split_store4(tok[i], (uint2*)g_Ah + i, (uint2*)g_Al + i);
    } else if (b < 17408) {
        size_t i = (size_t)(b - 16384) * 256 + threadIdx.x;
        split_store4(W[i], (uint2*)g_Wh + i, (uint2*)g_Wl + i);
    } else if (b < 18048) {
        int i = (b - 17408) * 256 + threadIdx.x;
        if (i < 160 * 1024) {
            int d = i / 160, j = i % 160;
            float v = 0.f;
            if (j < 128) { int e = j >> 4, r = j & 15; v = A[(size_t)e * 16384 + d * 16 + r]; }
            else if (j < 136) v = Wg[(size_t)d * 8 + (j - 128)];
            __nv_bfloat16 h, l; split2(v, h, l);
            g_Bc_h[i] = h; g_Bc_l[i] = l;
        }
    } else {
        size_t i = (size_t)(b - 18048) * 256 + threadIdx.x;
        split_store4(B[i], (uint2*)g_Bf_h + i, (uint2*)g_Bf_l + i);
    }
}

// ---------------- GEMM1 + fused router (BM=64) ----------
// h_ext[64,160] = tokens @ Bc ; then per-row top-2 softmax, gated H, outputs.
// BM=64, BN=160, BK=32, 256 threads, 8 warps 4(m)x2(n), warp tile 16x80.
__global__ __launch_bounds__(256, 2) void gemm1_mma(float* __restrict__ out_logits,
                                                    float* __restrict__ out_sel,
                                                    float* __restrict__ out_wts) {
    constexpr int BM = 64, BN = 160, BK = 32, NST = 4;
    constexpr int HN = BN / 2, N8 = HN / 8, NT2 = N8 / 2;   // 80, 10, 5
    constexpr int LDA = BK + 8, LDB = BN + 8;
    constexpr uint32_t ASZ = BM * LDA * 2, BSZ = BK * LDB * 2;
    constexpr uint32_t STG = ASZ + BSZ;
    constexpr int LDH = 164;

    extern __shared__ __align__(16) char smem[];
    const uint32_t sA = s2u(smem);
    const uint32_t sB = sA + ASZ;
    float* hsm = (float*)smem;  // epilogue reuse: [64][164] fp32

    const int tid = threadIdx.x, w = tid >> 5, lane = tid & 31;
    const int wm = w & 3, wn = w >> 2;
    const int lr = lane & 15, lc8 = (lane >> 4) * 8;
    const int bm = blockIdx.y * BM;

    const __nv_bfloat16* Asrc[3] = { g_Ah, g_Ah, g_Al };
    const __nv_bfloat16* Bsrc[3] = { g_Bc_h, g_Bc_l, g_Bc_h };
    constexpr int TOT = 3072 / BK;   // 96

    auto load_tile = [&](int t, int buf) {
        int kg = t * BK;
        int si = kg >> 10;
        int ko = kg & 1023;
        const __nv_bfloat16* Ap = Asrc[si] + (size_t)bm * 1024 + ko;
        const __nv_bfloat16* Bp = Bsrc[si] + (size_t)ko * 160;
        const uint32_t dA = sA + buf * STG, dB = sB + buf * STG;
        {   // A: 64 rows x 4 chunks = 256 cp16
            int row = tid >> 2, c = tid & 3;
            cp16(dA + (row * LDA + c * 8) * 2, Ap + (size_t)row * 1024 + c * 8);
        }
        #pragma unroll
        for (int i = 0; i < 3; i++) {                 // B: 640 chunks
            int idx = tid + i * 256;
            if (idx < 640) {
                int row = idx / 20, c = idx % 20;
                cp16(dB + (row * LDB + c * 8) * 2, Bp + (size_t)row * 160 + c * 8);
            }
        }
    };

    float acc[N8][4];
    #pragma unroll
    for (int nt = 0; nt < N8; nt++)
        #pragma unroll
        for (int q = 0; q < 4; q++) acc[nt][q] = 0.f;

    const uint32_t aab = sA + ((wm * 16 + lr) * LDA + lc8) * 2;
    uint32_t bab[NT2];
    #pragma unroll
    for (int nt2 = 0; nt2 < NT2; nt2++)
        bab[nt2] = sB + (lr * LDB + wn * HN + nt2 * 16 + lc8) * 2;

    #pragma unroll
    for (int p = 0; p < NST - 1; p++) { load_tile(p, p); CP_COMMIT(); }

    for (int t = 0; t < TOT; t++) {
        const int buf = t & (NST - 1);
        asm volatile("cp.async.wait_group %0;" :: "n"(NST - 2));
        __syncthreads();
        if (t + NST - 1 < TOT) load_tile(t + NST - 1, (t + NST - 1) & (NST - 1));
        CP_COMMIT();

        const uint32_t off = buf * STG;
        #pragma unroll
        for (int kk = 0; kk < BK; kk += 16) {
            uint32_t af[4];
            ldsm4(af, aab + off + kk * 2);
            #pragma unroll
            for (int nt2 = 0; nt2 < NT2; nt2++) {
                uint32_t bf[4];
                ldsm4t(bf, bab[nt2] + off + kk * LDB * 2);
                mma_bf16(acc[2 * nt2],     af, bf[0], bf[1]);
                mma_bf16(acc[2 * nt2 + 1], af, bf[2], bf[3]);
            }
        }
    }

    // ---- epilogue: stage h_ext into smem ----
    asm volatile("cp.async.wait_group 0;" ::: "memory");
    __syncthreads();
    {
        int r0 = wm * 16 + (lane >> 2);
        #pragma unroll
        for (int nt = 0; nt < N8; nt++) {
            int c0 = wn * HN + nt * 8 + 2 * (lane & 3);
            hsm[r0 * LDH + c0]           = acc[nt][0];
            hsm[r0 * LDH + c0 + 1]       = acc[nt][1];
            hsm[(r0 + 8) * LDH + c0]     = acc[nt][2];
            hsm[(r0 + 8) * LDH + c0 + 1] = acc[nt][3];
        }
    }
    __syncthreads();

    // ---- fused router: 4 threads per row ----
    {
        const int r = tid >> 2, q = tid & 3;
        const int n = bm + r;
        const float* hrow = hsm + r * LDH;
        float v0 = -1e30f; int i0 = 0;
        #pragma unroll
        for (int e = 0; e < 8; e++) {
            float v = hrow[128 + e];
            if (v > v0) { v0 = v; i0 = e; }
        }
        float v1 = -1e30f; int i1 = 0;
        #pragma unroll
        for (int e = 0; e < 8; e++) {
            float v = hrow[128 + e];
            if (e != i0 && v > v1) { v1 = v; i1 = e; }
        }
        float e1v = __expf(v1 - v0);
        float p0 = 1.0f / (1.0f + e1v);
        float p1 = e1v * p0;
        if (q == 0) {
            #pragma unroll
            for (int e = 0; e < 8; e++)
                out_logits[(size_t)n * 8 + e] = hrow[128 + e];
            out_sel[(size_t)n * 2 + 0] = (float)i0;
            out_sel[(size_t)n * 2 + 1] = (float)i1;
            out_wts[(size_t)n * 2 + 0] = p0;
            out_wts[(size_t)n * 2 + 1] = p1;
        }
        const float s0 = SCALING * p0, s1 = SCALING * p1;
        const int jbase = q * 32;
        #pragma unroll
        for (int j4 = 0; j4 < 32; j4 += 4) {
            int j = jbase + j4;
            int e = j >> 4;
            float g = (e == i0) ? s0 : ((e == i1) ? s1 : 0.f);
            float4 h4 = *(const float4*)(hrow + j);
            __nv_bfloat16 h0, h1, h2, h3, l0, l1, l2, l3;
            split2(h4.x * g, h0, l0); split2(h4.y * g, h1, l1);
            split2(h4.z * g, h2, l2); split2(h4.w * g, h3, l3);
            *(uint2*)&g_Hh[(size_t)n * 128 + j] = make_uint2(pack2(h0, h1), pack2(h2, h3));
            *(uint2*)&g_Hl[(size_t)n * 128 + j] = make_uint2(pack2(l0, l1), pack2(l2, l3));
        }
    }
}

// ---------------- GEMM2 (BM=128, BN=128, BK=32, NST=5, 128 thr) -----------
// out = tokens @ W + H @ Bf ; K = 3x1024 (base split) + 1x128 (LoRA hi-only).
// LoRA lo-correction passes dropped: lora term is ~7% of output, so single-pass
// bf16 there adds ~2.8e-4 norm-relative error (threshold 1e-3).
__global__ __launch_bounds__(128, 2) void gemm2_mma(float* __restrict__ outp) {
    constexpr int BM = 128, BN = 128, BK = 32, NST = 5;
    constexpr int LDA = BK + 8, LDB = BN + 8;
    constexpr uint32_t ASZ = BM * LDA * 2, BSZ = BK * LDB * 2;
    constexpr uint32_t STG = ASZ + BSZ;

    extern __shared__ __align__(16) char smem[];
    const uint32_t sA = s2u(smem);
    const uint32_t sB = sA + ASZ;

    const int tid = threadIdx.x, w = tid >> 5, lane = tid & 31;
    const int wm = w & 1, wn = w >> 1;
    const int lr = lane & 15, lc8 = (lane >> 4) * 8;
    const int bm = blockIdx.y * BM;
    const int bn = blockIdx.x * BN;

    const __nv_bfloat16* Asrc[4] = { g_Ah, g_Ah, g_Al, g_Hh };
    const __nv_bfloat16* Bsrc[4] = { g_Wh, g_Wl, g_Wh, g_Bf_h };
    constexpr int TOT = 3200 / BK;   // 100

    auto load_tile = [&](int t, int buf) {
        int kg = t * BK;
        int si, ko, as;
        if (kg < 3072) { si = kg >> 10; ko = kg & 1023; as = 1024; }
        else { si = 3; ko = kg - 3072; as = 128; }
        const __nv_bfloat16* Ap = Asrc[si] + (size_t)bm * as + ko;
        const __nv_bfloat16* Bp = Bsrc[si] + (size_t)ko * 1024 + bn;
        const uint32_t dA = sA + buf * STG, dB = sB + buf * STG;
        #pragma unroll
        for (int i = 0; i < 4; i++) {                 // A: 512 cp16
            int idx = tid + i * 128;
            int row = idx >> 2, c = idx & 3;
            cp16(dA + (row * LDA + c * 8) * 2, Ap + (size_t)row * as + c * 8);
        }
        #pragma unroll
        for (int i = 0; i < 4; i++) {                 // B: 512 cp16
            int idx = tid + i * 128;
            int row = idx >> 4, c = idx & 15;
            cp16(dB + (row * LDB + c * 8) * 2, Bp + (size_t)row * 1024 + c * 8);
        }
    };

    float acc[4][8][4];
    #pragma unroll
    for (int mt = 0; mt < 4; mt++)
        #pragma unroll
        for (int nt = 0; nt < 8; nt++)
            #pragma unroll
            for (int q = 0; q < 4; q++) acc[mt][nt][q] = 0.f;

    uint32_t aab[4], bab[4];
    #pragma unroll
    for (int mt = 0; mt < 4; mt++)
        aab[mt] = sA + ((wm * 64 + mt * 16 + lr) * LDA + lc8) * 2;
    #pragma unroll
    for (int nt2 = 0; nt2 < 4; nt2++)
        bab[nt2] = sB + (lr * LDB + wn * 64 + nt2 * 16 + lc8) * 2;

    #pragma unroll
    for (int p = 0; p < NST - 1; p++) { load_tile(p, p); CP_COMMIT(); }

    int buf = 0, pbuf = NST - 1;
    for (int t = 0; t < TOT; t++) {
        asm volatile("cp.async.wait_group %0;" :: "n"(NST - 2));
        __syncthreads();
        if (t + NST - 1 < TOT) load_tile(t + NST - 1, pbuf);
        CP_COMMIT();
        if (++pbuf == NST) pbuf = 0;

        const uint32_t off = buf * STG;
        if (++buf == NST) buf = 0;
        #pragma unroll
        for (int kk = 0; kk < BK; kk += 16) {
            uint32_t af[4][4];
            #pragma unroll
            for (int mt = 0; mt < 4; mt++)
                ldsm4(af[mt], aab[mt] + off + kk * 2);
            #pragma unroll
            for (int nt2 = 0; nt2 < 4; nt2++) {
                uint32_t bf[4];
                ldsm4t(bf, bab[nt2] + off + kk * LDB * 2);
                #pragma unroll
                for (int mt = 0; mt < 4; mt++) {
                    mma_bf16(acc[mt][2 * nt2],     af[mt], bf[0], bf[1]);
                    mma_bf16(acc[mt][2 * nt2 + 1], af[mt], bf[2], bf[3]);
                }
            }
        }
    }

    #pragma unroll
    for (int mt = 0; mt < 4; mt++) {
        int r0 = bm + wm * 64 + mt * 16 + (lane >> 2);
        #pragma unroll
        for (int nt = 0; nt < 8; nt++) {
            int c0 = bn + wn * 64 + nt * 8 + 2 * (lane & 3);
            *(float2*)(outp + (size_t)r0 * D_OUT + c0) =
                make_float2(acc[mt][nt][0], acc[mt][nt][1]);
            *(float2*)(outp + (size_t)(r0 + 8) * D_OUT + c0) =
                make_float2(acc[mt][nt][2], acc[mt][nt][3]);
        }
    }
}

// ---------------- Launch ----------------
extern "C" void kernel_launch(void* const* d_in, const int* in_sizes, int n_in,
                              void* d_out, int out_size) {
    const float* tokens = (const float*)d_in[0];
    const float* W_base = (const float*)d_in[1];
    const float* A      = (const float*)d_in[2];
    const float* B      = (const float*)d_in[3];
    const float* W_gate = (const float*)d_in[4];

    float* out        = (float*)d_out;
    float* out_logits = out + (size_t)N_TOK * D_OUT;
    float* out_sel    = out_logits + (size_t)N_TOK * N_EXP;
    float* out_wts    = out_sel + (size_t)N_TOK * 2;

    const int smem1 = 4 * (64 * 40 + 32 * 168) * 2;        // 63,488 B
    const int smem2 = 5 * (128 * 40 + 32 * 136) * 2;       // 94,720 B

    cudaFuncSetAttribute(gemm1_mma,
                         cudaFuncAttributeMaxDynamicSharedMemorySize, smem1);
    cudaFuncSetAttribute(gemm2_mma,
                         cudaFuncAttributeMaxDynamicSharedMemorySize, smem2);

    conv_all<<<18176, 256>>>((const float4*)tokens, (const float4*)W_base,
                             A, W_gate, (const float4*)B);

    gemm1_mma<<<dim3(1, N_TOK / 64), 256, smem1>>>(out_logits, out_sel, out_wts);

    gemm2_mma<<<dim3(D_OUT / 128, N_TOK / 128), 128, smem2>>>(out);
}